// round 3
// baseline (speedup 1.0000x reference)
#include <cuda_runtime.h>
#include <math.h>

#define NB 8
#define NC 20
#define NROWS 160
#define NP 8732
#define NM 16
#define QUADP 2183          // NP/4 exactly
#define K1T 256
#define K3T 512
#define THRESH_BITS 0x3F000000  // bits of 0.5f

// -------- global scratch (zero-init at load; g_best/g_hist self-restored by K3) --------
__device__ unsigned long long g_best[NROWS * NM];
__device__ unsigned int       g_hist[NROWS * 256];
__device__ __align__(16) float g_ce[NROWS * NP];
__device__ float g_pl1[NROWS * 4], g_pcp[NROWS * 4];
__device__ int   g_pnp[NROWS * 4];
__device__ float g_rconf[NROWS], g_rl1[NROWS], g_rnp[NROWS];

// -------- helpers (shared by K1 and K3 for bit-identical results) --------
__device__ __forceinline__ float fmax_i(float a, float b) {
    return __int_as_float(max(__float_as_int(a), __float_as_int(b)));
}
__device__ __forceinline__ float fmin_i(float a, float b) {
    return __int_as_float(min(__float_as_int(a), __float_as_int(b)));
}

__device__ __forceinline__ float iou_bp(float4 b, float barea,
                                        float px1, float py1, float px2, float py2,
                                        float parea) {
    float iw = fmin_i(b.z, px2) - fmax_i(b.x, px1);
    float ih = fmin_i(b.w, py2) - fmax_i(b.y, py1);
    iw = fmax_i(iw, 0.f); ih = fmax_i(ih, 0.f);
    float inter = iw * ih;
    return __fdividef(inter, barea + parea - inter);
}

__device__ __forceinline__ float ce_from_scores(float2 sc, int cls) {
    float mx  = fmaxf(sc.x, sc.y);
    float lse = mx + __logf(1.f + __expf(-fabsf(sc.x - sc.y)));
    return lse - (cls ? sc.y : sc.x);
}

__device__ __forceinline__ float l1_term(float4 b, float4 pr, float4 pl) {
    float cx = (b.x + b.z) * 0.5f, cy = (b.y + b.w) * 0.5f;
    float w  = b.z - b.x,          h  = b.w - b.y;
    float gx = __fdividef((cx - pr.x) * 10.f, pr.z);
    float gy = __fdividef((cy - pr.y) * 10.f, pr.w);
    float gw = __logf(__fdividef(w, pr.z)) * 5.f;
    float gh = __logf(__fdividef(h, pr.w)) * 5.f;
    return fabsf(pl.x - gx) + fabsf(pl.y - gy) + fabsf(pl.z - gw) + fabsf(pl.w - gh);
}

__device__ __forceinline__ float warp_sum(float v) {
#pragma unroll
    for (int o = 16; o; o >>= 1) v += __shfl_down_sync(0xffffffffu, v, o);
    return v;
}

// -------- K1 chunk: 8 boxes over this block's prior range --------
template <int CH>
__device__ __forceinline__ void k1_chunk(
    int row, int p0, int tid,
    const float4* __restrict__ prior4,
    const float2* __restrict__ sc2,
    const float4* __restrict__ pl4,
    const float4* s_bx4, const float* s_area, const int* s_lab,
    int* s_tmp, unsigned long long* s_best, unsigned* s_hist,
    float& l1a, float& cpa, int& npa)
{
    float4 bb[8]; float ba[8];
#pragma unroll
    for (int i = 0; i < 8; i++) { bb[i] = s_bx4[CH * 8 + i]; ba[i] = s_area[CH * 8 + i]; }
    unsigned bbest[8];
#pragma unroll
    for (int i = 0; i < 8; i++) bbest[i] = 0u;

    for (int it = 0; it < 9; it++) {
        int off = it * K1T + tid;
        bool act = off < QUADP;
        int p = p0 + (act ? off : 0);
        float4 pr = prior4[p];
        float hw = pr.z * 0.5f, hh = pr.w * 0.5f;
        float px1 = pr.x - hw, py1 = pr.y - hh;
        float px2 = pr.x + hw, py2 = pr.y + hh;
        if (!act) { px1 = px2 = -1e30f; py1 = py2 = -1e30f; }  // forces iou = 0
        float parea = (px2 - px1) * (py2 - py1);

        int best = (CH == 0) ? 0 : s_tmp[act ? off : 0];
#pragma unroll
        for (int i = 0; i < 8; i++) {
            float iou = iou_bp(bb[i], ba[i], px1, py1, px2, py2, parea);
            int hb = __float_as_int(iou) & 0xFFFFFFF0;
            best = max(best, hb | (CH * 8 + i));                         // per-prior argmax over m
            bbest[i] = max(bbest[i], (unsigned)hb | (unsigned)(15 - it)); // per-box best over p
        }
        if (CH == 0) {
            if (act) s_tmp[off] = best;
        } else {
            float ce_neg = 0.f;
            if (act) {
                int bm  = best & 15;
                int cls = (best >= THRESH_BITS) ? s_lab[bm] : 0;
                float2 sc = sc2[p];
                float ce  = ce_from_scores(sc, cls);
                ce_neg = ce;
                if (cls) {
                    npa++; cpa += ce;
                    l1a += l1_term(s_bx4[bm], pr, pl4[p]);
                    ce_neg = 0.f;
                }
                g_ce[(size_t)row * NP + p] = ce_neg;
            }
            // fused first-radix-pass histogram (top byte), warp-aggregated
            unsigned byte = act ? (__float_as_uint(ce_neg) >> 24)
                                : (0x100u + (unsigned)(tid & 31));
            unsigned peers = __match_any_sync(0xffffffffu, byte);
            if (act && (int)(__ffs(peers) - 1) == (tid & 31))
                atomicAdd(&s_hist[byte], (unsigned)__popc(peers));
        }
    }
    // flush per-box bests (exact p recovered from iteration code)
#pragma unroll
    for (int i = 0; i < 8; i++) {
        unsigned kb = bbest[i];
        int itw = 15 - (int)(kb & 15u);
        int pw  = p0 + itw * K1T + tid;
        if (pw >= NP) pw = NP - 1;   // only reachable with value bits 0
        unsigned long long key =
            ((unsigned long long)(kb & 0xFFFFFFF0u) << 32) | (unsigned)(NP - 1 - pw);
        atomicMax(&s_best[CH * 8 + i], key);
    }
}

// -------- K1: 640 blocks (4 per row), provisional match + CE/L1 + hist --------
__global__ __launch_bounds__(K1T) void mb_k1(
    const float* __restrict__ ploc, const float* __restrict__ pscore,
    const float* __restrict__ boxes, const int* __restrict__ labels,
    const float* __restrict__ priors)
{
    __shared__ float4 s_bx4[NM];
    __shared__ float  s_area[NM];
    __shared__ int    s_lab[NM];
    __shared__ int    s_tmp[QUADP];
    __shared__ unsigned long long s_best[NM];
    __shared__ unsigned s_hist[256];
    __shared__ float s_wl1[8], s_wcp[8];
    __shared__ int   s_wnp[8];

    const int row = blockIdx.x >> 2, quad = blockIdx.x & 3, tid = threadIdx.x;
    const int p0 = quad * QUADP;

    if (tid < NM) {
        const float* b = boxes + ((size_t)row * NM + tid) * 4;
        float4 v = make_float4(b[0], b[1], b[2], b[3]);
        s_bx4[tid]  = v;
        s_area[tid] = (v.z - v.x) * (v.w - v.y);
        s_lab[tid]  = labels[(size_t)row * NM + tid];
        s_best[tid] = 0ull;
    }
    s_hist[tid] = 0u;
    __syncthreads();

    const float4* prior4 = (const float4*)priors;
    const float2* sc2 = (const float2*)pscore + (size_t)row * NP;
    const float4* pl4 = (const float4*)ploc   + (size_t)row * NP;

    float l1a = 0.f, cpa = 0.f; int npa = 0;
    k1_chunk<0>(row, p0, tid, prior4, sc2, pl4, s_bx4, s_area, s_lab,
                s_tmp, s_best, s_hist, l1a, cpa, npa);
    k1_chunk<1>(row, p0, tid, prior4, sc2, pl4, s_bx4, s_area, s_lab,
                s_tmp, s_best, s_hist, l1a, cpa, npa);

    l1a = warp_sum(l1a); cpa = warp_sum(cpa);
    float npf = warp_sum((float)npa);
    const int wid = tid >> 5, lane = tid & 31;
    if (lane == 0) { s_wl1[wid] = l1a; s_wcp[wid] = cpa; s_wnp[wid] = (int)npf; }
    __syncthreads();
    if (tid == 0) {
        float a = 0.f, b = 0.f; int c = 0;
        for (int w = 0; w < 8; w++) { a += s_wl1[w]; b += s_wcp[w]; c += s_wnp[w]; }
        g_pl1[row * 4 + quad] = a; g_pcp[row * 4 + quad] = b; g_pnp[row * 4 + quad] = c;
    }
    if (tid < NM) atomicMax(&g_best[row * NM + tid], s_best[tid]);
    unsigned hv = s_hist[tid];
    if (hv) atomicAdd(&g_hist[row * 256 + tid], hv);
}

// -------- selection scan over 256-bin histogram (single warp) --------
__device__ __forceinline__ void select_scan(unsigned* s_hist, unsigned* s_pref, int* s_kk,
                                            unsigned pref, int shift, int lane, int tid)
{
    if (tid < 32) {
        int kk = *s_kk;          // read BEFORE any lane may write
        __syncwarp();
        unsigned h[8]; unsigned lsum = 0;
        const int base = (31 - lane) * 8;   // lane 0 -> bins 248..255
#pragma unroll
        for (int i = 0; i < 8; i++) { h[i] = s_hist[base + i]; lsum += h[i]; }
        unsigned incl = lsum;
#pragma unroll
        for (int off = 1; off < 32; off <<= 1) {
            unsigned v = __shfl_up_sync(0xffffffffu, incl, off);
            if (lane >= off) incl += v;
        }
        unsigned excl = incl - lsum;
        if (excl < (unsigned)kk && incl >= (unsigned)kk) {
            unsigned cum = excl;
#pragma unroll
            for (int i = 7; i >= 0; i--) {
                unsigned cnt = h[i];
                if (cum + cnt >= (unsigned)kk) {
                    *s_pref = pref | ((unsigned)(base + i) << shift);
                    *s_kk   = kk - (int)cum;
                    break;
                }
                cum += cnt;
            }
        }
    }
}

// -------- K3: 160 blocks, forced-match fix-up + radix select + row output --------
__global__ __launch_bounds__(K3T) void mb_k3(
    const float* __restrict__ ploc, const float* __restrict__ pscore,
    const float* __restrict__ boxes, const int* __restrict__ labels,
    const float* __restrict__ priors)
{
    __shared__ __align__(16) float s_ce[NP];
    __shared__ unsigned s_hist[256];
    __shared__ float4 s_bx4[NM];
    __shared__ float  s_area[NM];
    __shared__ int    s_lab[NM];
    __shared__ float  s_dl1[NM], s_dcp[NM], s_dnp[NM];
    __shared__ float  s_sumgt, s_conf, s_l1, s_npf;
    __shared__ int    s_kk;
    __shared__ unsigned s_pref;

    const int row = blockIdx.x, tid = threadIdx.x, lane = tid & 31;

    const float4* gce4 = (const float4*)(g_ce + (size_t)row * NP);
    float4* sce4 = (float4*)s_ce;
    for (int i = tid; i < QUADP; i += K3T) sce4[i] = gce4[i];
    if (tid < 256) { s_hist[tid] = g_hist[row * 256 + tid]; g_hist[row * 256 + tid] = 0u; }
    if (tid < NM) {
        const float* b = boxes + ((size_t)row * NM + tid) * 4;
        float4 v = make_float4(b[0], b[1], b[2], b[3]);
        s_bx4[tid]  = v;
        s_area[tid] = (v.z - v.x) * (v.w - v.y);
        s_lab[tid]  = labels[(size_t)row * NM + tid];
        s_dl1[tid] = 0.f; s_dcp[tid] = 0.f; s_dnp[tid] = 0.f;
    }
    if (tid == 0) {
        float a = 0.f, b = 0.f; int c = 0;
        for (int q = 0; q < 4; q++) { a += g_pl1[row*4+q]; b += g_pcp[row*4+q]; c += g_pnp[row*4+q]; }
        s_l1 = a; s_conf = b; s_npf = (float)c; s_sumgt = 0.f;
    }
    __syncthreads();

    const float4* prior4 = (const float4*)priors;
    const float2* sc2 = (const float2*)pscore + (size_t)row * NP;
    const float4* pl4 = (const float4*)ploc   + (size_t)row * NP;

    // ---- forced-match fix-up (16 lanes, last-write-wins via owner = highest m) ----
    if (tid < NM) {
        unsigned long long key = g_best[row * NM + tid];
        g_best[row * NM + tid] = 0ull;     // restore for next replay
        int pp = NP - 1 - (int)(unsigned)(key & 0xFFFFFFFFull);
        unsigned peers = __match_any_sync(0x0000FFFFu, pp);
        if ((31 - __clz(peers)) == tid) {   // final owner of this prior
            float4 pr = prior4[pp];
            float hw = pr.z * 0.5f, hh = pr.w * 0.5f;
            float px1 = pr.x - hw, py1 = pr.y - hh;
            float px2 = pr.x + hw, py2 = pr.y + hh;
            float parea = (px2 - px1) * (py2 - py1);
            int best = 0;
#pragma unroll
            for (int m = 0; m < NM; m++) {
                float iou = iou_bp(s_bx4[m], s_area[m], px1, py1, px2, py2, parea);
                best = max(best, (__float_as_int(iou) & 0xFFFFFFF0) | m);
            }
            int bm = best & 15;
            int cls_old = (best >= THRESH_BITS) ? s_lab[bm] : 0;
            float2 sc = sc2[pp];
            float4 pl = pl4[pp];
            float ce_old = ce_from_scores(sc, cls_old);
            float dl1 = 0.f, dcp = 0.f, dnp = 0.f;
            unsigned ob, nb;
            if (cls_old) { dnp -= 1.f; dcp -= ce_old; dl1 -= l1_term(s_bx4[bm], pr, pl); ob = 0u; }
            else ob = __float_as_uint(ce_old) >> 24;
            int cls_new = s_lab[tid];
            float ce_new = ce_from_scores(sc, cls_new);
            float cenew;
            if (cls_new) { dnp += 1.f; dcp += ce_new; dl1 += l1_term(s_bx4[tid], pr, pl); cenew = 0.f; }
            else cenew = ce_new;
            nb = __float_as_uint(cenew) >> 24;
            s_ce[pp] = cenew;
            if (ob != nb) { atomicSub(&s_hist[ob], 1u); atomicAdd(&s_hist[nb], 1u); }
            s_dl1[tid] = dl1; s_dcp[tid] = dcp; s_dnp[tid] = dnp;
        }
    }
    __syncthreads();
    if (tid == 0) {
        for (int m = 0; m < NM; m++) { s_l1 += s_dl1[m]; s_conf += s_dcp[m]; s_npf += s_dnp[m]; }
    }
    __syncthreads();

    const int npos = (int)s_npf;
    int K = 3 * npos; if (K > NP) K = NP;
    float conf_hard = 0.f;

    if (K > 0) {
        if (tid == 0) { s_pref = 0u; s_kk = K; }
        __syncthreads();
        // top-byte pass from the prebuilt histogram (no data sweep)
        select_scan(s_hist, &s_pref, &s_kk, 0u, 24, lane, tid);
        __syncthreads();
#pragma unroll 1
        for (int pass = 2; pass >= 0; pass--) {
            const int shift = pass * 8;
            if (tid < 256) s_hist[tid] = 0u;
            __syncthreads();
            const unsigned pref   = s_pref;
            const unsigned maskHi = 0xFFFFFFFFu << (shift + 8);
            for (int base = 0; base < NP; base += K3T) {
                int p = base + tid;
                bool predt = false; unsigned bin = 0x100u + (unsigned)lane;
                if (p < NP) {
                    unsigned kb = __float_as_uint(s_ce[p]);
                    if ((kb & maskHi) == pref) { predt = true; bin = (kb >> shift) & 0xFF; }
                }
                unsigned peers = __match_any_sync(0xffffffffu, bin);
                if (predt && (int)(__ffs(peers) - 1) == lane)
                    atomicAdd(&s_hist[bin], (unsigned)__popc(peers));
            }
            __syncthreads();
            select_scan(s_hist, &s_pref, &s_kk, pref, shift, lane, tid);
            __syncthreads();
        }
        const unsigned T = s_pref;
        float sum_gt = 0.f;
        for (int p = tid; p < NP; p += K3T) {
            float v = s_ce[p];
            if (__float_as_uint(v) > T) sum_gt += v;
        }
        sum_gt = warp_sum(sum_gt);
        if (lane == 0) atomicAdd(&s_sumgt, sum_gt);
        __syncthreads();
        if (tid == 0) conf_hard = s_sumgt + (float)s_kk * __uint_as_float(T);
    }

    if (tid == 0) {
        g_rconf[row] = s_conf + conf_hard;
        g_rl1[row]   = s_l1;
        g_rnp[row]   = s_npf;
    }
}

// -------- finalize --------
__global__ void mb_fin(float* __restrict__ out) {
    int t = threadIdx.x;   // 32 threads
    float v = 0.f;
    if (t < NC) {
        float conf = 0.f, l1 = 0.f, np = 0.f;
#pragma unroll
        for (int n = 0; n < NB; n++) {
            int r = n * NC + t;
            conf += g_rconf[r]; l1 += g_rl1[r]; np += g_rnp[r];
        }
        if (np > 0.f)
            v = (conf + l1 / fmaxf(np * 4.f, 1.f)) / fmaxf(np, 1.f);
    }
    v = warp_sum(v);
    if (t == 0) out[0] = v / (float)NC;
}

extern "C" void kernel_launch(void* const* d_in, const int* in_sizes, int n_in,
                              void* d_out, int out_size) {
    const float* ploc   = (const float*)d_in[0];
    const float* pscore = (const float*)d_in[1];
    const float* boxes  = (const float*)d_in[2];
    const int*   labels = (const int*)d_in[3];
    const float* priors = (const float*)d_in[4];
    float* out = (float*)d_out;

    mb_k1<<<NROWS * 4, K1T>>>(ploc, pscore, boxes, labels, priors);
    mb_k3<<<NROWS, K3T>>>(ploc, pscore, boxes, labels, priors);
    mb_fin<<<1, 32>>>(out);
}